// round 14
// baseline (speedup 1.0000x reference)
#include <cuda_runtime.h>
#include <cuda_fp16.h>
#include <math.h>
#include <stdint.h>

// ---------------- problem constants ----------------
#define BB 8
#define CC 640
#define HW 4096     // 64*64
#define KDIM 160
#define MR 4
#define GROUPS 32
#define CPG 20      // 640/32
#define QT 32       // qp partial tiles

// ---------------- scratch (device globals; no allocs allowed) ----------------
__device__ float g_tpart[4*MR*CC*64];              // vd split-K partials
__device__ float g_qp  [BB*KDIM*QT];
__device__ float g_gn  [BB*GROUPS*2];
__device__ float g_gnpart[(long long)BB*CC*32*2];  // per (b, chan, x-tile) sum/sumsq
__device__ float g_attnw[BB*2];
__device__ int   g_attni[BB*2];
__device__ float g_zeros[2*CC];

// fp16 operands / intermediates
__device__ __half g_wh  [2*CC*2*CC];
__device__ __half g_w2h [CC*CC];
__device__ __half g_qph [256*CC];                 // qp_w zero-padded to 256 rows
__device__ __half g_xh  [(long long)BB*CC*HW];    // x      [b][c][p]
__device__ __half g_dech[(long long)MR*CC*HW];    // dec    [m][c][p]
__device__ __half g_ydh [(long long)MR*2*CC*HW];  // Yd[m]
__device__ __half g_f1h [(long long)BB*CC*HW];    // f1 (pre-GN)
__device__ __half g_gate[(long long)BB*CC*HW];    // sigmoid(gate-pre)
__device__ __half g_f2h [(long long)BB*CC*HW];    // f2

__device__ __forceinline__ float gelu_f(float v){
    return 0.5f*v*(1.0f + erff(v*0.70710678118654752f));
}

// ================= mma.sync helpers (sm_80+ base ISA) =================
__device__ __forceinline__ uint32_t smem_u32(const void* p){
    uint32_t a;
    asm("{ .reg .u64 t; cvta.to.shared.u64 t, %1; cvt.u32.u64 %0, t; }" : "=r"(a) : "l"(p));
    return a;
}
__device__ __forceinline__ void cpa16(uint32_t dst, const void* src){
    asm volatile("cp.async.cg.shared.global [%0], [%1], 16;" :: "r"(dst), "l"(src));
}
__device__ __forceinline__ void ldm_x4(uint32_t (&r)[4], uint32_t addr){
    asm volatile("ldmatrix.sync.aligned.m8n8.x4.shared.b16 {%0,%1,%2,%3}, [%4];"
        : "=r"(r[0]),"=r"(r[1]),"=r"(r[2]),"=r"(r[3]) : "r"(addr));
}
// x4 trans: two adjacent k16xn8 B fragments in one instruction.
__device__ __forceinline__ void ldm_x4t(uint32_t (&r)[4], uint32_t addr){
    asm volatile("ldmatrix.sync.aligned.m8n8.x4.trans.shared.b16 {%0,%1,%2,%3}, [%4];"
        : "=r"(r[0]),"=r"(r[1]),"=r"(r[2]),"=r"(r[3]) : "r"(addr));
}
__device__ __forceinline__ void mma_f16(float (&d)[4], const uint32_t (&a)[4],
                                        uint32_t b0, uint32_t b1){
    asm volatile("mma.sync.aligned.m16n8k16.row.col.f32.f16.f16.f32 "
        "{%0,%1,%2,%3}, {%4,%5,%6,%7}, {%8,%9}, {%0,%1,%2,%3};"
        : "+f"(d[0]),"+f"(d[1]),"+f"(d[2]),"+f"(d[3])
        : "r"(a[0]),"r"(a[1]),"r"(a[2]),"r"(a[3]), "r"(b0),"r"(b1));
}

// ================= pure-fp16 tensor-core GEMM (mma.sync, trans-B) =================
// Y[bz, o, p] = sum_k Wh[o,k] * Bh[k,p] (+bias); B from channel-major [bz][c][p].
// CTA tile 128x128, K-chunks of 64, 3-stage cp.async pipeline.
// EPI 1: sigmoid-gate blend (fn2 out); 2: gelu+pixel-reduce (qp);
// EPI 3: fn1 (yd-blend + f1 fp16 + GN partials + gate sigmoid); 4: fp16 store (yd).
#define KC 64
#define APITCH 144                // A tile row pitch (128B data + 16 pad; conflict-free)
#define A_TILE (128*APITCH)       // 18432
#define BPITCH 272                // B tile row pitch (256B data + 16 pad)
#define B_TILE (KC*BPITCH)        // 17408
#define STAGE_B (A_TILE + B_TILE) // 35840
#define NSTAGE 3

template<int EPI>
__global__ void __launch_bounds__(256,2) gemm_tc(
    const __half* __restrict__ Wh, long long sA,
    const __half* __restrict__ Bh, long long sBpl,
    const float* __restrict__ biasa, const float* __restrict__ biasb, int rowSplit,
    float* __restrict__ Y, long long sY, int Kiter,
    const __half* __restrict__ gate_in,        // EPI1
    const __half* __restrict__ xres,           // EPI1 (fp16 residual)
    __half* __restrict__ gate_out,             // EPI3
    float* __restrict__ gnpart,                // EPI3
    const __half* __restrict__ ydbase,         // EPI3
    float* __restrict__ qpout)                 // EPI2
{
    extern __shared__ char smem[];
    const uint32_t sb = smem_u32(smem);
    const int tid = threadIdx.x, wid = tid >> 5, lane = tid & 31;
    const int warpM = wid >> 2, warpN = wid & 3;
    const int pBase = blockIdx.x * 128, oBase = blockIdx.y * 128, bz = blockIdx.z;
    const long long P = 4096;

    const __half* a_g = Wh + (long long)oBase * sA;
    const __half* b_p = Bh + (long long)bz * sBpl + pBase;

    float acc[4][4][4];
#pragma unroll
    for (int a = 0; a < 4; a++)
#pragma unroll
        for (int b = 0; b < 4; b++)
#pragma unroll
            for (int c = 0; c < 4; c++) acc[a][b][c] = 0.f;

    const uint32_t aoff = (uint32_t)((warpM*64 + (lane & 15)) * APITCH + (lane >> 4) * 16);
    const uint32_t boff4 = (uint32_t)((lane & 15) * BPITCH + ((lane >> 4) << 4) + warpN * 64);

    const int nCh = Kiter / KC;

    auto load_stage = [&](int st, int c0){
        uint32_t base = sb + st * STAGE_B;
#pragma unroll
        for (int i = 0; i < 8; i++){
            int t = tid + (i << 8);
            if (t < 1024){
                int r = t >> 3, ck = t & 7;          // A: 128 rows x 8 chunks of 16B
                cpa16(base + (uint32_t)(r*APITCH + ck*16),
                      a_g + (long long)r * sA + c0 + (ck << 3));
            } else {
                int u = t - 1024, r = u >> 4, ck = u & 15;  // B: 64 k-rows x 16 chunks
                cpa16(base + A_TILE + (uint32_t)(r*BPITCH + ck*16),
                      b_p + (long long)(c0 + r) * P + (ck << 3));
            }
        }
        asm volatile("cp.async.commit_group;" ::: "memory");
    };

    load_stage(0, 0);
    if (nCh > 1) load_stage(1, KC);

    for (int ch = 0; ch < nCh; ch++){
        if (ch + 2 < nCh){
            load_stage((ch + 2) % NSTAGE, (ch + 2) * KC);
            asm volatile("cp.async.wait_group 2;" ::: "memory");
        } else if (ch + 1 < nCh){
            asm volatile("cp.async.wait_group 1;" ::: "memory");
        } else {
            asm volatile("cp.async.wait_group 0;" ::: "memory");
        }
        __syncthreads();

        uint32_t base = sb + (ch % NSTAGE) * STAGE_B;
        uint32_t SA = base, SB = base + A_TILE;
#pragma unroll
        for (int ks = 0; ks < 4; ks++){
            uint32_t ako = ks * 32;              // 16 fp16 = 32 B along A row
            uint32_t bko = ks * 16 * BPITCH;     // 16 k-rows down B tile
            uint32_t b4a[4], b4b[4];
            ldm_x4t(b4a, SB + boff4 + bko);        // n fragments 0,1
            ldm_x4t(b4b, SB + boff4 + bko + 32);   // n fragments 2,3
#pragma unroll
            for (int mi = 0; mi < 4; mi++){
                uint32_t a[4];
                ldm_x4(a, SA + aoff + mi*16*APITCH + ako);
                mma_f16(acc[mi][0], a, b4a[0], b4a[1]);
                mma_f16(acc[mi][1], a, b4a[2], b4a[3]);
                mma_f16(acc[mi][2], a, b4b[0], b4b[1]);
                mma_f16(acc[mi][3], a, b4b[2], b4b[3]);
            }
        }
        __syncthreads();
    }

    // ---- epilogue: acc -> SMEM stage (pitch 132) -> coalesced out ----
    float* stage = (float*)smem;
#pragma unroll
    for (int mi = 0; mi < 4; mi++){
        int r0 = warpM*64 + mi*16 + (lane >> 2);
#pragma unroll
        for (int ni = 0; ni < 4; ni++){
            int col = warpN*32 + ni*8 + 2*(lane & 3);
            stage[r0*132 + col]       = acc[mi][ni][0];
            stage[r0*132 + col + 1]   = acc[mi][ni][1];
            stage[(r0+8)*132 + col]   = acc[mi][ni][2];
            stage[(r0+8)*132 + col+1] = acc[mi][ni][3];
        }
    }
    __syncthreads();

    if (EPI == 2){
        int r = tid >> 1, h = tid & 1;
        int o = oBase + r;
        float s = 0.f;
        if (o < KDIM){
            float bo = biasa[o];
            const float* row = stage + r * 132 + h * 64;
#pragma unroll 8
            for (int j = 0; j < 64; j++) s += gelu_f(row[j] + bo);
        }
        s += __shfl_xor_sync(0xffffffffu, s, 1);
        if (h == 0 && o < KDIM)
            qpout[((bz*KDIM) + o)*QT + blockIdx.x] = s;
        return;
    }

    if (EPI == 4){
        __half* Yh = (__half*)Y;
        for (int i = tid; i < 128 * 128; i += 256){
            int r = i >> 7, c = i & 127;
            int o = oBase + r;
            Yh[(long long)bz * sY + (long long)o * P + pBase + c]
                = __float2half_rn(stage[r * 132 + c]);
        }
        return;
    }

    if (EPI == 3){
        float a0 = g_attnw[bz*2], a1 = g_attnw[bz*2+1];
        const long long YDS = (long long)2*CC*HW;
        const __half* yd0 = ydbase + (long long)g_attni[bz*2]   * YDS;
        const __half* yd1 = ydbase + (long long)g_attni[bz*2+1] * YDS;
        bool isF1 = (oBase < rowSplit);
        __half* Yh = (__half*)Y;
        for (int i = tid; i < 128 * 128; i += 256){
            int r = i >> 7, c = i & 127;
            int o = oBase + r; long long p = pBase + c;
            long long q = (long long)o * P + p;
            float v = stage[r * 132 + c];
            float bo = (o < rowSplit) ? biasa[o] : biasb[o - rowSplit];
            v += bo + a0 * __half2float(yd0[q]) + a1 * __half2float(yd1[q]);
            if (isF1){
                Yh[(long long)bz * sY + q] = __float2half_rn(v);
                stage[r * 132 + c] = v;          // exact fp32 for GN partials
            } else {
                float g = 1.0f / (1.0f + expf(-v));
                gate_out[((long long)bz * CC + (o - rowSplit)) * P + p] = __float2half_rn(g);
            }
        }
        if (isF1){
            __syncthreads();
            int r = tid >> 1, h = tid & 1;
            const float* row = stage + r * 132 + h * 64;
            float s = 0.f, ss = 0.f;
#pragma unroll 8
            for (int j = 0; j < 64; j++){ float v = row[j]; s += v; ss += v*v; }
            s  += __shfl_xor_sync(0xffffffffu, s, 1);
            ss += __shfl_xor_sync(0xffffffffu, ss, 1);
            if (h == 0){
                int o = oBase + r;
                float* dst = gnpart + ((long long)(bz*CC + o)*32 + blockIdx.x)*2;
                dst[0] = s; dst[1] = ss;
            }
        }
        return;
    }

    // EPI == 1 : fn2 output + sigmoid-gate blend (fp16 gate + fp16 residual)
    for (int i = tid; i < 128 * 128; i += 256){
        int r = i >> 7, c = i & 127;
        float v = stage[r * 132 + c];
        int o = oBase + r; long long p = pBase + c;
        v += biasa[o];
        long long q = ((long long)bz * CC + o) * P + p;
        float g = __half2float(gate_in[q]);
        float xr = __half2float(xres[q]);
        Y[(long long)bz * sY + (long long)o * P + p] = g * v + (1.0f - g) * xr;
    }
}

// ================= conversion helpers =================
__global__ void wconv_all(const float* __restrict__ w1, const float* __restrict__ wg,
                          const float* __restrict__ w2, const float* __restrict__ wq){
    int i = blockIdx.x * 256 + threadIdx.x;
    const int N1 = CC*2*CC, N2 = 2*N1, N3 = N2 + CC*CC, N4 = N3 + 256*CC;
    if (i < N1)      g_wh[i] = __float2half_rn(w1[i]);
    else if (i < N2) g_wh[i] = __float2half_rn(wg[i - N1]);
    else if (i < N3) g_w2h[i - N2] = __float2half_rn(w2[i - N2]);
    else if (i < N4){
        int j = i - N3;
        g_qph[j] = __float2half_rn((j < KDIM*CC) ? wq[j] : 0.f);
    }
}

__global__ void xconv(const float* __restrict__ src, __half* __restrict__ dst){
    long long i4 = (long long)blockIdx.x * 256 + threadIdx.x;
    float4 v = ((const float4*)src)[i4];
    __half2* D = (__half2*)(dst + (i4<<2));
    D[0] = __halves2half2(__float2half_rn(v.x), __float2half_rn(v.y));
    D[1] = __halves2half2(__float2half_rn(v.z), __float2half_rn(v.w));
}

// ---------------- vd GEMM, split-K x4 (writes partials, no bias) ----------------
constexpr int GK = 16;

__global__ __launch_bounds__(256) void vd_gemm(
    const float* __restrict__ Wa,
    const float* __restrict__ Xa, long long sXa)
{
    __shared__ float As[GK][64];
    __shared__ float Bs[GK][64];

    const int tid = threadIdx.x;
    const int tx = tid & 15, ty = tid >> 4;
    const int kc = blockIdx.x;
    const int oBase = blockIdx.y * 64;
    const int m = blockIdx.z;
    const int kBeg = kc * 160;

    float acc[4][4];
#pragma unroll
    for (int i = 0; i < 4; i++)
#pragma unroll
        for (int j = 0; j < 4; j++) acc[i][j] = 0.f;

    for (int c0 = kBeg; c0 < kBeg + 160; c0 += GK){
        {
            int i = tid >> 2;
            int j4 = (tid & 3) << 2;
            float4 w = *(const float4*)(Wa + (long long)(oBase + i)*CC + c0 + j4);
            As[j4+0][i] = w.x; As[j4+1][i] = w.y; As[j4+2][i] = w.z; As[j4+3][i] = w.w;
        }
        {
            int j = tid >> 4;
            int n4 = (tid & 15) << 2;
            const float* xp = Xa + m*sXa + (long long)(c0 + j)*64;
            *(float4*)&Bs[j][n4] = *(const float4*)(xp + n4);
        }
        __syncthreads();
#pragma unroll
        for (int kk = 0; kk < GK; kk++){
            float a[4], b[4];
            float4 t = *(const float4*)&As[kk][ty*4];
            a[0]=t.x; a[1]=t.y; a[2]=t.z; a[3]=t.w;
            float4 u = *(const float4*)&Bs[kk][tx*4];
            b[0]=u.x; b[1]=u.y; b[2]=u.z; b[3]=u.w;
#pragma unroll
            for (int i = 0; i < 4; i++)
#pragma unroll
                for (int j = 0; j < 4; j++)
                    acc[i][j] = fmaf(a[i], b[j], acc[i][j]);
        }
        __syncthreads();
    }

    float* dst = g_tpart + ((long long)(kc*MR + m)*CC)*64;
#pragma unroll
    for (int i = 0; i < 4; i++){
        int o = oBase + ty*4 + i;
        *(float4*)(dst + (long long)o*64 + tx*4) =
            make_float4(acc[i][0], acc[i][1], acc[i][2], acc[i][3]);
    }
}

// ---------------- attention: q reduce, cosine sims, top-2, softmax ----------------
__global__ void attn_kernel(const float* __restrict__ mem_keys){
    __shared__ float qs[BB*KDIM];
    int tid = threadIdx.x;
    for (int idx = tid; idx < BB*KDIM; idx += 256){
        const float* p = g_qp + (long long)idx*QT;
        float s = 0.f;
        for (int t = 0; t < QT; t++) s += p[t];
        qs[idx] = s * (1.0f/4096.0f);
    }
    __syncthreads();
    if (tid < BB){
        int b = tid;
        const float* q = qs + b*KDIM;
        float qn = 0.f;
        for (int j = 0; j < KDIM; j++) qn += q[j]*q[j];
        qn = fmaxf(sqrtf(qn), 1e-12f);
        float v[MR];
        for (int m = 0; m < MR; m++){
            const float* kk = mem_keys + m*KDIM;
            float kn = 0.f, d = 0.f;
            for (int j = 0; j < KDIM; j++){ kn += kk[j]*kk[j]; d += q[j]*kk[j]; }
            kn = fmaxf(sqrtf(kn), 1e-12f);
            v[m] = d/(qn*kn);
        }
        int i0 = 0;
        for (int m = 1; m < MR; m++) if (v[m] > v[i0]) i0 = m;
        int i1 = -1;
        for (int m = 0; m < MR; m++){
            if (m == i0) continue;
            if (i1 < 0 || v[m] > v[i1]) i1 = m;
        }
        float e1 = expf((v[i1]-v[i0])*10.0f);
        float a0 = 1.0f/(1.0f+e1);
        float a1 = e1/(1.0f+e1);
        g_attnw[b*2] = a0; g_attnw[b*2+1] = a1;
        g_attni[b*2] = i0; g_attni[b*2+1] = i1;
    }
}

// ---------------- bilinear 8->64 upsample + gelu + dw3x3 -> fp16 ----------------
__global__ __launch_bounds__(256) void up_gelu_dw(
    const float* __restrict__ wdw, const float* __restrict__ bdw,
    const float* __restrict__ vbias)
{
    int m = blockIdx.x / CC, c = blockIdx.x % CC;
    __shared__ float sm[64][65];
    __shared__ float tt[64];
    int tid = threadIdx.x;
    if (tid < 64){
        float s = vbias[c];
#pragma unroll
        for (int kc = 0; kc < 4; kc++)
            s += g_tpart[((long long)(kc*MR + m)*CC + c)*64 + tid];
        tt[tid] = s;
    }
    __syncthreads();
    for (int i = tid; i < 1024; i += 256){
        int p = i << 2, h = p >> 6, w0 = p & 63;
        float shf = h*0.125f - 0.4375f;
        int ih = (int)floorf(shf);
        float fh = shf - (float)ih;
        int h0 = ih < 0 ? 0 : ih;
        int h1 = (ih+1 > 7) ? 7 : ih+1;
#pragma unroll
        for (int q2 = 0; q2 < 4; q2++){
            int w = w0 + q2;
            float swf = w*0.125f - 0.4375f;
            int iw = (int)floorf(swf);
            float fw = swf - (float)iw;
            int wA = iw < 0 ? 0 : iw;
            int wB = (iw+1 > 7) ? 7 : iw+1;
            float top = (1.f-fw)*tt[h0*8+wA] + fw*tt[h0*8+wB];
            float bot = (1.f-fw)*tt[h1*8+wA] + fw*tt[h1*8+wB];
            float v = (1.f-fh)*top + fh*bot;
            sm[h][w] = gelu_f(v);
        }
    }
    __syncthreads();
    float w9[9];
#pragma unroll
    for (int t = 0; t < 9; t++) w9[t] = wdw[c*9+t];
    float bb = bdw[c];
    __half* dh = g_dech + ((long long)m*CC + c)*HW;
    for (int i = tid; i < 1024; i += 256){
        int p = i << 2, h = p >> 6, w0 = p & 63;
        float ov[4];
#pragma unroll
        for (int q2 = 0; q2 < 4; q2++){
            int w = w0 + q2;
            float s = bb;
#pragma unroll
            for (int ky = 0; ky < 3; ky++){
                int hh = h + ky - 1;
                if ((unsigned)hh > 63u) continue;
#pragma unroll
                for (int kx = 0; kx < 3; kx++){
                    int ww = w + kx - 1;
                    if ((unsigned)ww > 63u) continue;
                    s = fmaf(w9[ky*3+kx], sm[hh][ww], s);
                }
            }
            ov[q2] = s;
        }
        __half2* H = (__half2*)(dh + p);
        H[0] = __halves2half2(__float2half_rn(ov[0]), __float2half_rn(ov[1]));
        H[1] = __halves2half2(__float2half_rn(ov[2]), __float2half_rn(ov[3]));
    }
}

// ---------------- group-norm statistics (reduce fused partials) ----------------
__global__ void gn_stats(){
    int b = blockIdx.x >> 5, g = blockIdx.x & 31;
    int tid = threadIdx.x;
    float s = 0.f, ss = 0.f;
    for (int i = tid; i < CPG*32; i += 256){
        int c = g*CPG + i/32, tx = i%32;
        const float* p = g_gnpart + ((long long)(b*CC + c)*32 + tx)*2;
        s += p[0]; ss += p[1];
    }
    __shared__ float sh1[256], sh2[256];
    sh1[tid] = s; sh2[tid] = ss;
    __syncthreads();
    for (int st = 128; st > 0; st >>= 1){
        if (tid < st){ sh1[tid] += sh1[tid+st]; sh2[tid] += sh2[tid+st]; }
        __syncthreads();
    }
    if (tid == 0){
        const float inv = 1.0f/(CPG*HW);
        float mu = sh1[0]*inv;
        float var = sh2[0]*inv - mu*mu;
        g_gn[blockIdx.x*2]   = mu;
        g_gn[blockIdx.x*2+1] = rsqrtf(var + 1e-5f);
    }
}

// ---------------- group-norm + gelu + depthwise 3x3 (fp16 in/out) ----------------
__global__ __launch_bounds__(256) void gn_gelu_dw(
    const float* __restrict__ gamma, const float* __restrict__ beta,
    const float* __restrict__ wdw, const float* __restrict__ bdw)
{
    int b = blockIdx.x / CC, c = blockIdx.x % CC;
    __shared__ float sm[64][65];
    int tid = threadIdx.x;
    const __half2* src = (const __half2*)(g_f1h + ((long long)b*CC + c)*HW);
    int g = c / CPG;
    float mu = g_gn[(b*GROUPS+g)*2], rs = g_gn[(b*GROUPS+g)*2+1];
    float ga = gamma[c]*rs;
    float be = beta[c] - mu*ga;
    for (int i = tid; i < 1024; i += 256){
        __half2 v01 = src[2*i], v23 = src[2*i+1];
        int p = i << 2, h = p >> 6, w0 = p & 63;
        sm[h][w0]   = gelu_f(__low2float(v01)*ga + be);
        sm[h][w0+1] = gelu_f(__high2float(v01)*ga + be);
        sm[h][w0+2] = gelu_f(__low2float(v23)*ga + be);
        sm[h][w0+3] = gelu_f(__high2float(v23)*ga + be);
    }
    __syncthreads();
    float w9[9];
#pragma unroll
    for (int t = 0; t < 9; t++) w9[t] = wdw[c*9+t];
    float bb = bdw[c];
    __half* dh = g_f2h + ((long long)b*CC + c)*HW;
    for (int i = tid; i < 1024; i += 256){
        int p = i << 2, h = p >> 6, w0 = p & 63;
        float ov[4];
#pragma unroll
        for (int q2 = 0; q2 < 4; q2++){
            int w = w0 + q2;
            float s = bb;
#pragma unroll
            for (int ky = 0; ky < 3; ky++){
                int hh = h + ky - 1;
                if ((unsigned)hh > 63u) continue;
#pragma unroll
                for (int kx = 0; kx < 3; kx++){
                    int ww = w + kx - 1;
                    if ((unsigned)ww > 63u) continue;
                    s = fmaf(w9[ky*3+kx], sm[hh][ww], s);
                }
            }
            ov[q2] = s;
        }
        __half2* H = (__half2*)(dh + p);
        H[0] = __halves2half2(__float2half_rn(ov[0]), __float2half_rn(ov[1]));
        H[1] = __halves2half2(__float2half_rn(ov[2]), __float2half_rn(ov[3]));
    }
}

// ---------------- host launcher ----------------
extern "C" void kernel_launch(void* const* d_in, const int* in_sizes, int n_in,
                              void* d_out, int out_size)
{
    const float* x         = (const float*)d_in[0];
    const float* qp_w      = (const float*)d_in[1];
    const float* qp_b      = (const float*)d_in[2];
    const float* mem_keys  = (const float*)d_in[3];
    const float* mem_values= (const float*)d_in[4];
    const float* vd_w1     = (const float*)d_in[5];
    const float* vd_b1     = (const float*)d_in[6];
    const float* vd_wdw    = (const float*)d_in[7];
    const float* vd_bdw    = (const float*)d_in[8];
    const float* fn_w1     = (const float*)d_in[9];
    const float* fn_b1     = (const float*)d_in[10];
    const float* fn_gamma  = (const float*)d_in[11];
    const float* fn_beta   = (const float*)d_in[12];
    const float* fn_wdw    = (const float*)d_in[13];
    const float* fn_bdw    = (const float*)d_in[14];
    const float* fn_w2     = (const float*)d_in[15];
    const float* fn_b2     = (const float*)d_in[16];
    const float* fg_w      = (const float*)d_in[17];
    const float* fg_b      = (const float*)d_in[18];
    float* out = (float*)d_out;
    (void)in_sizes; (void)n_in; (void)out_size;

    float *p_qp, *p_zeros, *p_gnpart;
    __half *p_wh, *p_w2h, *p_qph, *p_xh, *p_dech, *p_ydh, *p_f1h, *p_gate, *p_f2h;
    cudaGetSymbolAddress((void**)&p_qp,    g_qp);
    cudaGetSymbolAddress((void**)&p_zeros, g_zeros);
    cudaGetSymbolAddress((void**)&p_gnpart,g_gnpart);
    cudaGetSymbolAddress((void**)&p_wh,    g_wh);
    cudaGetSymbolAddress((void**)&p_w2h,   g_w2h);
    cudaGetSymbolAddress((void**)&p_qph,   g_qph);
    cudaGetSymbolAddress((void**)&p_xh,    g_xh);
    cudaGetSymbolAddress((void**)&p_dech,  g_dech);
    cudaGetSymbolAddress((void**)&p_ydh,   g_ydh);
    cudaGetSymbolAddress((void**)&p_f1h,   g_f1h);
    cudaGetSymbolAddress((void**)&p_gate,  g_gate);
    cudaGetSymbolAddress((void**)&p_f2h,   g_f2h);

    const int DSM = NSTAGE * STAGE_B;   // 107520 (2 CTAs/SM: 215KB <= 228KB)
    cudaFuncSetAttribute(gemm_tc<1>, cudaFuncAttributeMaxDynamicSharedMemorySize, DSM);
    cudaFuncSetAttribute(gemm_tc<2>, cudaFuncAttributeMaxDynamicSharedMemorySize, DSM);
    cudaFuncSetAttribute(gemm_tc<3>, cudaFuncAttributeMaxDynamicSharedMemorySize, DSM);
    cudaFuncSetAttribute(gemm_tc<4>, cudaFuncAttributeMaxDynamicSharedMemorySize, DSM);

    const long long sX = (long long)CC*HW;

    // side stream + fork/join events (capture-legal; fresh per call)
    cudaStream_t s1;
    cudaStreamCreateWithFlags(&s1, cudaStreamNonBlocking);
    cudaEvent_t e0, e1;
    cudaEventCreateWithFlags(&e0, cudaEventDisableTiming);
    cudaEventCreateWithFlags(&e1, cudaEventDisableTiming);

    // 0) all weight conversions (one launch, stream 0)
    {
        const int NTOT = 2*(CC*2*CC) + CC*CC + 256*CC;
        wconv_all<<<(NTOT+255)/256,256>>>(fn_w1, fg_w, fn_w2, qp_w);
    }

    // fork: chain B (dec pipeline) on s1
    cudaEventRecord(e0, 0);
    cudaStreamWaitEvent(s1, e0, 0);

    // chain B (s1): vd split-K -> upsample/dw -> Yd GEMM
    vd_gemm<<<dim3(4,10,MR),256,0,s1>>>(vd_w1, mem_values, (long long)CC*64);
    up_gelu_dw<<<MR*CC,256,0,s1>>>(vd_wdw, vd_bdw, vd_b1);
    gemm_tc<4><<<dim3(32,10,MR),256,DSM,s1>>>(
        p_wh + CC, 2*CC,
        p_dech, sX,
        p_zeros, p_zeros, 2*CC,
        (float*)p_ydh, (long long)2*CC*HW, CC,
        nullptr, nullptr, nullptr, nullptr, nullptr, nullptr);
    cudaEventRecord(e1, s1);

    // chain A (stream 0): x fp16 -> qp GEMM -> attention
    xconv<<<(int)((long long)BB*CC*HW/4/256),256>>>(x, p_xh);
    gemm_tc<2><<<dim3(QT,2,BB),256,DSM>>>(
        p_qph, CC, p_xh, sX,
        qp_b, qp_b, KDIM,
        nullptr, 0, CC,
        nullptr, nullptr, nullptr, nullptr, nullptr, p_qp);
    attn_kernel<<<1,256>>>(mem_keys);

    // join
    cudaStreamWaitEvent(0, e1, 0);

    // fn1 + gate GEMM; epilogue: yd-blend, f1 fp16 + GN partials, gate sigmoid fp16
    gemm_tc<3><<<dim3(32,10,BB),256,DSM>>>(
        p_wh, 2*CC,
        p_xh, sX,
        fn_b1, fg_b, CC,
        (float*)p_f1h, sX, CC,
        nullptr, nullptr, p_gate, p_gnpart, p_ydh, nullptr);

    // group-norm stats (reduce fused partials)
    gn_stats<<<BB*GROUPS,256>>>();

    // gn + gelu + depthwise (fp16 in/out)
    gn_gelu_dw<<<BB*CC,256>>>(fn_gamma, fn_beta, fn_wdw, fn_bdw);

    // fn2 GEMM + sigmoid-gate blend -> out
    gemm_tc<1><<<dim3(32,5,BB),256,DSM>>>(
        p_w2h, CC,
        p_f2h, sX,
        fn_b2, fn_b2, CC,
        out, sX, CC,
        p_gate, p_xh, nullptr, nullptr, nullptr, nullptr);
}

// round 16
// speedup vs baseline: 1.0134x; 1.0134x over previous
#include <cuda_runtime.h>
#include <cuda_fp16.h>
#include <math.h>
#include <stdint.h>

// ---------------- problem constants ----------------
#define BB 8
#define CC 640
#define HW 4096     // 64*64
#define KDIM 160
#define MR 4
#define GROUPS 32
#define CPG 20      // 640/32
#define QT 32       // qp partial tiles

// ---------------- scratch (device globals; no allocs allowed) ----------------
__device__ float g_tpart[4*MR*CC*64];              // vd split-K partials
__device__ float g_qp  [BB*KDIM*QT];
__device__ float g_gn  [BB*GROUPS*2];
__device__ float g_gnpart[(long long)BB*CC*32*2];  // per (b, chan, x-tile) sum/sumsq
__device__ float g_attnw[BB*2];
__device__ int   g_attni[BB*2];
__device__ float g_zeros[2*CC];

// fp16 operands / intermediates
__device__ __half g_wh  [2*CC*2*CC];
__device__ __half g_w2h [CC*CC];
__device__ __half g_qph [256*CC];                 // qp_w zero-padded to 256 rows
__device__ __half g_xh  [(long long)BB*CC*HW];    // x      [b][c][p]
__device__ __half g_dech[(long long)MR*CC*HW];    // dec    [m][c][p]
__device__ __half g_ydh [(long long)MR*2*CC*HW];  // Yd[m]
__device__ __half g_f1h [(long long)BB*CC*HW];    // f1 (pre-GN)
__device__ __half g_gate[(long long)BB*CC*HW];    // sigmoid(gate-pre)
__device__ __half g_f2h [(long long)BB*CC*HW];    // f2

__device__ __forceinline__ float gelu_f(float v){
    return 0.5f*v*(1.0f + erff(v*0.70710678118654752f));
}

// ================= mma.sync helpers (sm_80+ base ISA) =================
__device__ __forceinline__ uint32_t smem_u32(const void* p){
    uint32_t a;
    asm("{ .reg .u64 t; cvta.to.shared.u64 t, %1; cvt.u32.u64 %0, t; }" : "=r"(a) : "l"(p));
    return a;
}
__device__ __forceinline__ void cpa16(uint32_t dst, const void* src){
    asm volatile("cp.async.cg.shared.global [%0], [%1], 16;" :: "r"(dst), "l"(src));
}
__device__ __forceinline__ void ldm_x4(uint32_t (&r)[4], uint32_t addr){
    asm volatile("ldmatrix.sync.aligned.m8n8.x4.shared.b16 {%0,%1,%2,%3}, [%4];"
        : "=r"(r[0]),"=r"(r[1]),"=r"(r[2]),"=r"(r[3]) : "r"(addr));
}
// x4 trans: two adjacent k16xn8 B fragments in one instruction.
__device__ __forceinline__ void ldm_x4t(uint32_t (&r)[4], uint32_t addr){
    asm volatile("ldmatrix.sync.aligned.m8n8.x4.trans.shared.b16 {%0,%1,%2,%3}, [%4];"
        : "=r"(r[0]),"=r"(r[1]),"=r"(r[2]),"=r"(r[3]) : "r"(addr));
}
__device__ __forceinline__ void mma_f16(float (&d)[4], const uint32_t (&a)[4],
                                        uint32_t b0, uint32_t b1){
    asm volatile("mma.sync.aligned.m16n8k16.row.col.f32.f16.f16.f32 "
        "{%0,%1,%2,%3}, {%4,%5,%6,%7}, {%8,%9}, {%0,%1,%2,%3};"
        : "+f"(d[0]),"+f"(d[1]),"+f"(d[2]),"+f"(d[3])
        : "r"(a[0]),"r"(a[1]),"r"(a[2]),"r"(a[3]), "r"(b0),"r"(b1));
}

// ================= pure-fp16 tensor-core GEMM (mma.sync, trans-B) =================
// Y[bz, o, p] = sum_k Wh[o,k] * Bh[k,p] (+bias); B from channel-major [bz][c][p].
// CTA tile 128x128, K-chunks of 64, 2-stage cp.async pipeline (champion config).
// EPI 1: sigmoid-gate blend (fn2 out); 2: gelu+pixel-reduce (qp);
// EPI 3: fn1 (yd-blend + f1 fp16 + GN partials + gate sigmoid); 4: fp16 store (yd).
#define KC 64
#define APITCH 144                // A tile row pitch (128B data + 16 pad; conflict-free)
#define A_TILE (128*APITCH)       // 18432
#define BPITCH 272                // B tile row pitch (256B data + 16 pad)
#define B_TILE (KC*BPITCH)        // 17408
#define STAGE_B (A_TILE + B_TILE) // 35840
#define NSTAGE 2

template<int EPI>
__global__ void __launch_bounds__(256,2) gemm_tc(
    const __half* __restrict__ Wh, long long sA,
    const __half* __restrict__ Bh, long long sBpl,
    const float* __restrict__ biasa, const float* __restrict__ biasb, int rowSplit,
    float* __restrict__ Y, long long sY, int Kiter,
    const __half* __restrict__ gate_in,        // EPI1
    const __half* __restrict__ xres,           // EPI1 (fp16 residual)
    __half* __restrict__ gate_out,             // EPI3
    float* __restrict__ gnpart,                // EPI3
    const __half* __restrict__ ydbase,         // EPI3
    float* __restrict__ qpout)                 // EPI2
{
    extern __shared__ char smem[];
    const uint32_t sb = smem_u32(smem);
    const int tid = threadIdx.x, wid = tid >> 5, lane = tid & 31;
    const int warpM = wid >> 2, warpN = wid & 3;
    const int pBase = blockIdx.x * 128, oBase = blockIdx.y * 128, bz = blockIdx.z;
    const long long P = 4096;

    const __half* a_g = Wh + (long long)oBase * sA;
    const __half* b_p = Bh + (long long)bz * sBpl + pBase;

    float acc[4][4][4];
#pragma unroll
    for (int a = 0; a < 4; a++)
#pragma unroll
        for (int b = 0; b < 4; b++)
#pragma unroll
            for (int c = 0; c < 4; c++) acc[a][b][c] = 0.f;

    const uint32_t aoff = (uint32_t)((warpM*64 + (lane & 15)) * APITCH + (lane >> 4) * 16);
    const uint32_t boff4 = (uint32_t)((lane & 15) * BPITCH + ((lane >> 4) << 4) + warpN * 64);

    const int nCh = Kiter / KC;

    auto load_stage = [&](int st, int c0){
        uint32_t base = sb + st * STAGE_B;
#pragma unroll
        for (int i = 0; i < 8; i++){
            int t = tid + (i << 8);
            if (t < 1024){
                int r = t >> 3, ck = t & 7;          // A: 128 rows x 8 chunks of 16B
                cpa16(base + (uint32_t)(r*APITCH + ck*16),
                      a_g + (long long)r * sA + c0 + (ck << 3));
            } else {
                int u = t - 1024, r = u >> 4, ck = u & 15;  // B: 64 k-rows x 16 chunks
                cpa16(base + A_TILE + (uint32_t)(r*BPITCH + ck*16),
                      b_p + (long long)(c0 + r) * P + (ck << 3));
            }
        }
        asm volatile("cp.async.commit_group;" ::: "memory");
    };

    load_stage(0, 0);

    for (int ch = 0; ch < nCh; ch++){
        if (ch + 1 < nCh){
            load_stage((ch + 1) & 1, (ch + 1) * KC);
            asm volatile("cp.async.wait_group 1;" ::: "memory");
        } else {
            asm volatile("cp.async.wait_group 0;" ::: "memory");
        }
        __syncthreads();

        uint32_t base = sb + (ch & 1) * STAGE_B;
        uint32_t SA = base, SB = base + A_TILE;
#pragma unroll
        for (int ks = 0; ks < 4; ks++){
            uint32_t ako = ks * 32;              // 16 fp16 = 32 B along A row
            uint32_t bko = ks * 16 * BPITCH;     // 16 k-rows down B tile
            uint32_t b4a[4], b4b[4];
            ldm_x4t(b4a, SB + boff4 + bko);        // n fragments 0,1
            ldm_x4t(b4b, SB + boff4 + bko + 32);   // n fragments 2,3
#pragma unroll
            for (int mi = 0; mi < 4; mi++){
                uint32_t a[4];
                ldm_x4(a, SA + aoff + mi*16*APITCH + ako);
                mma_f16(acc[mi][0], a, b4a[0], b4a[1]);
                mma_f16(acc[mi][1], a, b4a[2], b4a[3]);
                mma_f16(acc[mi][2], a, b4b[0], b4b[1]);
                mma_f16(acc[mi][3], a, b4b[2], b4b[3]);
            }
        }
        __syncthreads();
    }

    // ---- epilogue: acc -> SMEM stage (pitch 132) -> coalesced out ----
    float* stage = (float*)smem;
#pragma unroll
    for (int mi = 0; mi < 4; mi++){
        int r0 = warpM*64 + mi*16 + (lane >> 2);
#pragma unroll
        for (int ni = 0; ni < 4; ni++){
            int col = warpN*32 + ni*8 + 2*(lane & 3);
            stage[r0*132 + col]       = acc[mi][ni][0];
            stage[r0*132 + col + 1]   = acc[mi][ni][1];
            stage[(r0+8)*132 + col]   = acc[mi][ni][2];
            stage[(r0+8)*132 + col+1] = acc[mi][ni][3];
        }
    }
    __syncthreads();

    if (EPI == 2){
        int r = tid >> 1, h = tid & 1;
        int o = oBase + r;
        float s = 0.f;
        if (o < KDIM){
            float bo = biasa[o];
            const float* row = stage + r * 132 + h * 64;
#pragma unroll 8
            for (int j = 0; j < 64; j++) s += gelu_f(row[j] + bo);
        }
        s += __shfl_xor_sync(0xffffffffu, s, 1);
        if (h == 0 && o < KDIM)
            qpout[((bz*KDIM) + o)*QT + blockIdx.x] = s;
        return;
    }

    if (EPI == 4){
        __half* Yh = (__half*)Y;
        for (int i = tid; i < 128 * 128; i += 256){
            int r = i >> 7, c = i & 127;
            int o = oBase + r;
            Yh[(long long)bz * sY + (long long)o * P + pBase + c]
                = __float2half_rn(stage[r * 132 + c]);
        }
        return;
    }

    if (EPI == 3){
        float a0 = g_attnw[bz*2], a1 = g_attnw[bz*2+1];
        const long long YDS = (long long)2*CC*HW;
        const __half* yd0 = ydbase + (long long)g_attni[bz*2]   * YDS;
        const __half* yd1 = ydbase + (long long)g_attni[bz*2+1] * YDS;
        bool isF1 = (oBase < rowSplit);
        __half* Yh = (__half*)Y;
        for (int i = tid; i < 128 * 128; i += 256){
            int r = i >> 7, c = i & 127;
            int o = oBase + r; long long p = pBase + c;
            long long q = (long long)o * P + p;
            float v = stage[r * 132 + c];
            float bo = (o < rowSplit) ? biasa[o] : biasb[o - rowSplit];
            v += bo + a0 * __half2float(yd0[q]) + a1 * __half2float(yd1[q]);
            if (isF1){
                Yh[(long long)bz * sY + q] = __float2half_rn(v);
                stage[r * 132 + c] = v;          // exact fp32 for GN partials
            } else {
                float g = 1.0f / (1.0f + expf(-v));
                gate_out[((long long)bz * CC + (o - rowSplit)) * P + p] = __float2half_rn(g);
            }
        }
        if (isF1){
            __syncthreads();
            int r = tid >> 1, h = tid & 1;
            const float* row = stage + r * 132 + h * 64;
            float s = 0.f, ss = 0.f;
#pragma unroll 8
            for (int j = 0; j < 64; j++){ float v = row[j]; s += v; ss += v*v; }
            s  += __shfl_xor_sync(0xffffffffu, s, 1);
            ss += __shfl_xor_sync(0xffffffffu, ss, 1);
            if (h == 0){
                int o = oBase + r;
                float* dst = gnpart + ((long long)(bz*CC + o)*32 + blockIdx.x)*2;
                dst[0] = s; dst[1] = ss;
            }
        }
        return;
    }

    // EPI == 1 : fn2 output + sigmoid-gate blend (fp16 gate + fp16 residual)
    for (int i = tid; i < 128 * 128; i += 256){
        int r = i >> 7, c = i & 127;
        float v = stage[r * 132 + c];
        int o = oBase + r; long long p = pBase + c;
        v += biasa[o];
        long long q = ((long long)bz * CC + o) * P + p;
        float g = __half2float(gate_in[q]);
        float xr = __half2float(xres[q]);
        Y[(long long)bz * sY + (long long)o * P + p] = g * v + (1.0f - g) * xr;
    }
}

// ================= conversion helpers =================
__global__ void wconv_all(const float* __restrict__ w1, const float* __restrict__ wg,
                          const float* __restrict__ w2, const float* __restrict__ wq){
    int i = blockIdx.x * 256 + threadIdx.x;
    const int N1 = CC*2*CC, N2 = 2*N1, N3 = N2 + CC*CC, N4 = N3 + 256*CC;
    if (i < N1)      g_wh[i] = __float2half_rn(w1[i]);
    else if (i < N2) g_wh[i] = __float2half_rn(wg[i - N1]);
    else if (i < N3) g_w2h[i - N2] = __float2half_rn(w2[i - N2]);
    else if (i < N4){
        int j = i - N3;
        g_qph[j] = __float2half_rn((j < KDIM*CC) ? wq[j] : 0.f);
    }
}

__global__ void xconv(const float* __restrict__ src, __half* __restrict__ dst){
    long long i4 = (long long)blockIdx.x * 256 + threadIdx.x;
    float4 v = ((const float4*)src)[i4];
    __half2* D = (__half2*)(dst + (i4<<2));
    D[0] = __halves2half2(__float2half_rn(v.x), __float2half_rn(v.y));
    D[1] = __halves2half2(__float2half_rn(v.z), __float2half_rn(v.w));
}

// ---------------- vd GEMM, split-K x4 (writes partials, no bias) ----------------
constexpr int GK = 16;

__global__ __launch_bounds__(256) void vd_gemm(
    const float* __restrict__ Wa,
    const float* __restrict__ Xa, long long sXa)
{
    __shared__ float As[GK][64];
    __shared__ float Bs[GK][64];

    const int tid = threadIdx.x;
    const int tx = tid & 15, ty = tid >> 4;
    const int kc = blockIdx.x;
    const int oBase = blockIdx.y * 64;
    const int m = blockIdx.z;
    const int kBeg = kc * 160;

    float acc[4][4];
#pragma unroll
    for (int i = 0; i < 4; i++)
#pragma unroll
        for (int j = 0; j < 4; j++) acc[i][j] = 0.f;

    for (int c0 = kBeg; c0 < kBeg + 160; c0 += GK){
        {
            int i = tid >> 2;
            int j4 = (tid & 3) << 2;
            float4 w = *(const float4*)(Wa + (long long)(oBase + i)*CC + c0 + j4);
            As[j4+0][i] = w.x; As[j4+1][i] = w.y; As[j4+2][i] = w.z; As[j4+3][i] = w.w;
        }
        {
            int j = tid >> 4;
            int n4 = (tid & 15) << 2;
            const float* xp = Xa + m*sXa + (long long)(c0 + j)*64;
            *(float4*)&Bs[j][n4] = *(const float4*)(xp + n4);
        }
        __syncthreads();
#pragma unroll
        for (int kk = 0; kk < GK; kk++){
            float a[4], b[4];
            float4 t = *(const float4*)&As[kk][ty*4];
            a[0]=t.x; a[1]=t.y; a[2]=t.z; a[3]=t.w;
            float4 u = *(const float4*)&Bs[kk][tx*4];
            b[0]=u.x; b[1]=u.y; b[2]=u.z; b[3]=u.w;
#pragma unroll
            for (int i = 0; i < 4; i++)
#pragma unroll
                for (int j = 0; j < 4; j++)
                    acc[i][j] = fmaf(a[i], b[j], acc[i][j]);
        }
        __syncthreads();
    }

    float* dst = g_tpart + ((long long)(kc*MR + m)*CC)*64;
#pragma unroll
    for (int i = 0; i < 4; i++){
        int o = oBase + ty*4 + i;
        *(float4*)(dst + (long long)o*64 + tx*4) =
            make_float4(acc[i][0], acc[i][1], acc[i][2], acc[i][3]);
    }
}

// ---------------- attention: q reduce, cosine sims, top-2, softmax ----------------
__global__ void attn_kernel(const float* __restrict__ mem_keys){
    __shared__ float qs[BB*KDIM];
    int tid = threadIdx.x;
    for (int idx = tid; idx < BB*KDIM; idx += 256){
        const float* p = g_qp + (long long)idx*QT;
        float s = 0.f;
        for (int t = 0; t < QT; t++) s += p[t];
        qs[idx] = s * (1.0f/4096.0f);
    }
    __syncthreads();
    if (tid < BB){
        int b = tid;
        const float* q = qs + b*KDIM;
        float qn = 0.f;
        for (int j = 0; j < KDIM; j++) qn += q[j]*q[j];
        qn = fmaxf(sqrtf(qn), 1e-12f);
        float v[MR];
        for (int m = 0; m < MR; m++){
            const float* kk = mem_keys + m*KDIM;
            float kn = 0.f, d = 0.f;
            for (int j = 0; j < KDIM; j++){ kn += kk[j]*kk[j]; d += q[j]*kk[j]; }
            kn = fmaxf(sqrtf(kn), 1e-12f);
            v[m] = d/(qn*kn);
        }
        int i0 = 0;
        for (int m = 1; m < MR; m++) if (v[m] > v[i0]) i0 = m;
        int i1 = -1;
        for (int m = 0; m < MR; m++){
            if (m == i0) continue;
            if (i1 < 0 || v[m] > v[i1]) i1 = m;
        }
        float e1 = expf((v[i1]-v[i0])*10.0f);
        float a0 = 1.0f/(1.0f+e1);
        float a1 = e1/(1.0f+e1);
        g_attnw[b*2] = a0; g_attnw[b*2+1] = a1;
        g_attni[b*2] = i0; g_attni[b*2+1] = i1;
    }
}

// ---------------- bilinear 8->64 upsample + gelu + dw3x3 -> fp16 ----------------
__global__ __launch_bounds__(256) void up_gelu_dw(
    const float* __restrict__ wdw, const float* __restrict__ bdw,
    const float* __restrict__ vbias)
{
    int m = blockIdx.x / CC, c = blockIdx.x % CC;
    __shared__ float sm[64][65];
    __shared__ float tt[64];
    int tid = threadIdx.x;
    if (tid < 64){
        float s = vbias[c];
#pragma unroll
        for (int kc = 0; kc < 4; kc++)
            s += g_tpart[((long long)(kc*MR + m)*CC + c)*64 + tid];
        tt[tid] = s;
    }
    __syncthreads();
    for (int i = tid; i < 1024; i += 256){
        int p = i << 2, h = p >> 6, w0 = p & 63;
        float shf = h*0.125f - 0.4375f;
        int ih = (int)floorf(shf);
        float fh = shf - (float)ih;
        int h0 = ih < 0 ? 0 : ih;
        int h1 = (ih+1 > 7) ? 7 : ih+1;
#pragma unroll
        for (int q2 = 0; q2 < 4; q2++){
            int w = w0 + q2;
            float swf = w*0.125f - 0.4375f;
            int iw = (int)floorf(swf);
            float fw = swf - (float)iw;
            int wA = iw < 0 ? 0 : iw;
            int wB = (iw+1 > 7) ? 7 : iw+1;
            float top = (1.f-fw)*tt[h0*8+wA] + fw*tt[h0*8+wB];
            float bot = (1.f-fw)*tt[h1*8+wA] + fw*tt[h1*8+wB];
            float v = (1.f-fh)*top + fh*bot;
            sm[h][w] = gelu_f(v);
        }
    }
    __syncthreads();
    float w9[9];
#pragma unroll
    for (int t = 0; t < 9; t++) w9[t] = wdw[c*9+t];
    float bb = bdw[c];
    __half* dh = g_dech + ((long long)m*CC + c)*HW;
    for (int i = tid; i < 1024; i += 256){
        int p = i << 2, h = p >> 6, w0 = p & 63;
        float ov[4];
#pragma unroll
        for (int q2 = 0; q2 < 4; q2++){
            int w = w0 + q2;
            float s = bb;
#pragma unroll
            for (int ky = 0; ky < 3; ky++){
                int hh = h + ky - 1;
                if ((unsigned)hh > 63u) continue;
#pragma unroll
                for (int kx = 0; kx < 3; kx++){
                    int ww = w + kx - 1;
                    if ((unsigned)ww > 63u) continue;
                    s = fmaf(w9[ky*3+kx], sm[hh][ww], s);
                }
            }
            ov[q2] = s;
        }
        __half2* H = (__half2*)(dh + p);
        H[0] = __halves2half2(__float2half_rn(ov[0]), __float2half_rn(ov[1]));
        H[1] = __halves2half2(__float2half_rn(ov[2]), __float2half_rn(ov[3]));
    }
}

// ---------------- group-norm statistics (reduce fused partials) ----------------
__global__ void gn_stats(){
    int b = blockIdx.x >> 5, g = blockIdx.x & 31;
    int tid = threadIdx.x;
    float s = 0.f, ss = 0.f;
    for (int i = tid; i < CPG*32; i += 256){
        int c = g*CPG + i/32, tx = i%32;
        const float* p = g_gnpart + ((long long)(b*CC + c)*32 + tx)*2;
        s += p[0]; ss += p[1];
    }
    __shared__ float sh1[256], sh2[256];
    sh1[tid] = s; sh2[tid] = ss;
    __syncthreads();
    for (int st = 128; st > 0; st >>= 1){
        if (tid < st){ sh1[tid] += sh1[tid+st]; sh2[tid] += sh2[tid+st]; }
        __syncthreads();
    }
    if (tid == 0){
        const float inv = 1.0f/(CPG*HW);
        float mu = sh1[0]*inv;
        float var = sh2[0]*inv - mu*mu;
        g_gn[blockIdx.x*2]   = mu;
        g_gn[blockIdx.x*2+1] = rsqrtf(var + 1e-5f);
    }
}

// ---------------- group-norm + gelu + depthwise 3x3 (fp16 in/out) ----------------
__global__ __launch_bounds__(256) void gn_gelu_dw(
    const float* __restrict__ gamma, const float* __restrict__ beta,
    const float* __restrict__ wdw, const float* __restrict__ bdw)
{
    int b = blockIdx.x / CC, c = blockIdx.x % CC;
    __shared__ float sm[64][65];
    int tid = threadIdx.x;
    const __half2* src = (const __half2*)(g_f1h + ((long long)b*CC + c)*HW);
    int g = c / CPG;
    float mu = g_gn[(b*GROUPS+g)*2], rs = g_gn[(b*GROUPS+g)*2+1];
    float ga = gamma[c]*rs;
    float be = beta[c] - mu*ga;
    for (int i = tid; i < 1024; i += 256){
        __half2 v01 = src[2*i], v23 = src[2*i+1];
        int p = i << 2, h = p >> 6, w0 = p & 63;
        sm[h][w0]   = gelu_f(__low2float(v01)*ga + be);
        sm[h][w0+1] = gelu_f(__high2float(v01)*ga + be);
        sm[h][w0+2] = gelu_f(__low2float(v23)*ga + be);
        sm[h][w0+3] = gelu_f(__high2float(v23)*ga + be);
    }
    __syncthreads();
    float w9[9];
#pragma unroll
    for (int t = 0; t < 9; t++) w9[t] = wdw[c*9+t];
    float bb = bdw[c];
    __half* dh = g_f2h + ((long long)b*CC + c)*HW;
    for (int i = tid; i < 1024; i += 256){
        int p = i << 2, h = p >> 6, w0 = p & 63;
        float ov[4];
#pragma unroll
        for (int q2 = 0; q2 < 4; q2++){
            int w = w0 + q2;
            float s = bb;
#pragma unroll
            for (int ky = 0; ky < 3; ky++){
                int hh = h + ky - 1;
                if ((unsigned)hh > 63u) continue;
#pragma unroll
                for (int kx = 0; kx < 3; kx++){
                    int ww = w + kx - 1;
                    if ((unsigned)ww > 63u) continue;
                    s = fmaf(w9[ky*3+kx], sm[hh][ww], s);
                }
            }
            ov[q2] = s;
        }
        __half2* H = (__half2*)(dh + p);
        H[0] = __halves2half2(__float2half_rn(ov[0]), __float2half_rn(ov[1]));
        H[1] = __halves2half2(__float2half_rn(ov[2]), __float2half_rn(ov[3]));
    }
}

// ---------------- host launcher ----------------
extern "C" void kernel_launch(void* const* d_in, const int* in_sizes, int n_in,
                              void* d_out, int out_size)
{
    const float* x         = (const float*)d_in[0];
    const float* qp_w      = (const float*)d_in[1];
    const float* qp_b      = (const float*)d_in[2];
    const float* mem_keys  = (const float*)d_in[3];
    const float* mem_values= (const float*)d_in[4];
    const float* vd_w1     = (const float*)d_in[5];
    const float* vd_b1     = (const float*)d_in[6];
    const float* vd_wdw    = (const float*)d_in[7];
    const float* vd_bdw    = (const float*)d_in[8];
    const float* fn_w1     = (const float*)d_in[9];
    const float* fn_b1     = (const float*)d_in[10];
    const float* fn_gamma  = (const float*)d_in[11];
    const float* fn_beta   = (const float*)d_in[12];
    const float* fn_wdw    = (const float*)d_in[13];
    const float* fn_bdw    = (const float*)d_in[14];
    const float* fn_w2     = (const float*)d_in[15];
    const float* fn_b2     = (const float*)d_in[16];
    const float* fg_w      = (const float*)d_in[17];
    const float* fg_b      = (const float*)d_in[18];
    float* out = (float*)d_out;
    (void)in_sizes; (void)n_in; (void)out_size;

    float *p_qp, *p_zeros, *p_gnpart;
    __half *p_wh, *p_w2h, *p_qph, *p_xh, *p_dech, *p_ydh, *p_f1h, *p_gate, *p_f2h;
    cudaGetSymbolAddress((void**)&p_qp,    g_qp);
    cudaGetSymbolAddress((void**)&p_zeros, g_zeros);
    cudaGetSymbolAddress((void**)&p_gnpart,g_gnpart);
    cudaGetSymbolAddress((void**)&p_wh,    g_wh);
    cudaGetSymbolAddress((void**)&p_w2h,   g_w2h);
    cudaGetSymbolAddress((void**)&p_qph,   g_qph);
    cudaGetSymbolAddress((void**)&p_xh,    g_xh);
    cudaGetSymbolAddress((void**)&p_dech,  g_dech);
    cudaGetSymbolAddress((void**)&p_ydh,   g_ydh);
    cudaGetSymbolAddress((void**)&p_f1h,   g_f1h);
    cudaGetSymbolAddress((void**)&p_gate,  g_gate);
    cudaGetSymbolAddress((void**)&p_f2h,   g_f2h);

    const int DSM = NSTAGE * STAGE_B;   // 71680 (epilogue stage 67584 fits)
    cudaFuncSetAttribute(gemm_tc<1>, cudaFuncAttributeMaxDynamicSharedMemorySize, DSM);
    cudaFuncSetAttribute(gemm_tc<2>, cudaFuncAttributeMaxDynamicSharedMemorySize, DSM);
    cudaFuncSetAttribute(gemm_tc<3>, cudaFuncAttributeMaxDynamicSharedMemorySize, DSM);
    cudaFuncSetAttribute(gemm_tc<4>, cudaFuncAttributeMaxDynamicSharedMemorySize, DSM);

    const long long sX = (long long)CC*HW;

    // side stream + fork/join events (capture-legal; fresh per call)
    cudaStream_t s1;
    cudaStreamCreateWithFlags(&s1, cudaStreamNonBlocking);
    cudaEvent_t e0, e1;
    cudaEventCreateWithFlags(&e0, cudaEventDisableTiming);
    cudaEventCreateWithFlags(&e1, cudaEventDisableTiming);

    // chain B front (s1): vd split-K + upsample/dw need NO converted weights —
    // fork immediately, before any stream-0 work.
    vd_gemm<<<dim3(4,10,MR),256,0,s1>>>(vd_w1, mem_values, (long long)CC*64);
    up_gelu_dw<<<MR*CC,256,0,s1>>>(vd_wdw, vd_bdw, vd_b1);

    // stream 0: weight conversions, then signal e0 (Yd GEMM needs g_wh)
    {
        const int NTOT = 2*(CC*2*CC) + CC*CC + 256*CC;
        wconv_all<<<(NTOT+255)/256,256>>>(fn_w1, fg_w, fn_w2, qp_w);
    }
    cudaEventRecord(e0, 0);
    cudaStreamWaitEvent(s1, e0, 0);

    // chain B tail (s1): Yd GEMM
    gemm_tc<4><<<dim3(32,10,MR),256,DSM,s1>>>(
        p_wh + CC, 2*CC,
        p_dech, sX,
        p_zeros, p_zeros, 2*CC,
        (float*)p_ydh, (long long)2*CC*HW, CC,
        nullptr, nullptr, nullptr, nullptr, nullptr, nullptr);
    cudaEventRecord(e1, s1);

    // chain A (stream 0): x fp16 -> qp GEMM -> attention
    xconv<<<(int)((long long)BB*CC*HW/4/256),256>>>(x, p_xh);
    gemm_tc<2><<<dim3(QT,2,BB),256,DSM>>>(
        p_qph, CC, p_xh, sX,
        qp_b, qp_b, KDIM,
        nullptr, 0, CC,
        nullptr, nullptr, nullptr, nullptr, nullptr, p_qp);
    attn_kernel<<<1,256>>>(mem_keys);

    // join
    cudaStreamWaitEvent(0, e1, 0);

    // fn1 + gate GEMM; epilogue: yd-blend, f1 fp16 + GN partials, gate sigmoid fp16
    gemm_tc<3><<<dim3(32,10,BB),256,DSM>>>(
        p_wh, 2*CC,
        p_xh, sX,
        fn_b1, fg_b, CC,
        (float*)p_f1h, sX, CC,
        nullptr, nullptr, p_gate, p_gnpart, p_ydh, nullptr);

    // group-norm stats (reduce fused partials)
    gn_stats<<<BB*GROUPS,256>>>();

    // gn + gelu + depthwise (fp16 in/out)
    gn_gelu_dw<<<BB*CC,256>>>(fn_gamma, fn_beta, fn_wdw, fn_bdw);

    // fn2 GEMM + sigmoid-gate blend -> out
    gemm_tc<1><<<dim3(32,5,BB),256,DSM>>>(
        p_w2h, CC,
        p_f2h, sX,
        fn_b2, fn_b2, CC,
        out, sX, CC,
        p_gate, p_xh, nullptr, nullptr, nullptr, nullptr);
}

// round 17
// speedup vs baseline: 1.0221x; 1.0086x over previous
#include <cuda_runtime.h>
#include <cuda_fp16.h>
#include <math.h>
#include <stdint.h>

// ---------------- problem constants ----------------
#define BB 8
#define CC 640
#define HW 4096     // 64*64
#define KDIM 160
#define MR 4
#define GROUPS 32
#define CPG 20      // 640/32
#define QT 32       // qp partial tiles

// ---------------- scratch (device globals; no allocs allowed) ----------------
__device__ float g_tpart[4*MR*CC*64];              // vd split-K partials
__device__ float g_qp  [BB*KDIM*QT];
__device__ float g_gn  [BB*GROUPS*2];
__device__ float g_gnpart[(long long)BB*CC*32*2];  // per (b, chan, x-tile) sum/sumsq
__device__ float g_attnw[BB*2];
__device__ int   g_attni[BB*2];
__device__ float g_zeros[2*CC];

// fp16 operands / intermediates
__device__ __half g_wh  [2*CC*2*CC];
__device__ __half g_w2h [CC*CC];
__device__ __half g_qph [256*CC];                 // qp_w zero-padded to 256 rows
__device__ __half g_xh  [(long long)BB*CC*HW];    // x      [b][c][p]
__device__ __half g_dech[(long long)MR*CC*HW];    // dec    [m][c][p]
__device__ __half g_ydh [(long long)MR*2*CC*HW];  // Yd[m]
__device__ __half g_f1h [(long long)BB*CC*HW];    // f1 (pre-GN)
__device__ __half g_gate[(long long)BB*CC*HW];    // sigmoid(gate-pre)
__device__ __half g_f2h [(long long)BB*CC*HW];    // f2

__device__ __forceinline__ float gelu_f(float v){
    return 0.5f*v*(1.0f + erff(v*0.70710678118654752f));
}

// ================= mma.sync helpers (sm_80+ base ISA) =================
__device__ __forceinline__ uint32_t smem_u32(const void* p){
    uint32_t a;
    asm("{ .reg .u64 t; cvta.to.shared.u64 t, %1; cvt.u32.u64 %0, t; }" : "=r"(a) : "l"(p));
    return a;
}
__device__ __forceinline__ void cpa16(uint32_t dst, const void* src){
    asm volatile("cp.async.cg.shared.global [%0], [%1], 16;" :: "r"(dst), "l"(src));
}
__device__ __forceinline__ void ldm_x4(uint32_t (&r)[4], uint32_t addr){
    asm volatile("ldmatrix.sync.aligned.m8n8.x4.shared.b16 {%0,%1,%2,%3}, [%4];"
        : "=r"(r[0]),"=r"(r[1]),"=r"(r[2]),"=r"(r[3]) : "r"(addr));
}
// x4 trans: two adjacent k16xn8 B fragments in one instruction.
__device__ __forceinline__ void ldm_x4t(uint32_t (&r)[4], uint32_t addr){
    asm volatile("ldmatrix.sync.aligned.m8n8.x4.trans.shared.b16 {%0,%1,%2,%3}, [%4];"
        : "=r"(r[0]),"=r"(r[1]),"=r"(r[2]),"=r"(r[3]) : "r"(addr));
}
__device__ __forceinline__ void mma_f16(float (&d)[4], const uint32_t (&a)[4],
                                        uint32_t b0, uint32_t b1){
    asm volatile("mma.sync.aligned.m16n8k16.row.col.f32.f16.f16.f32 "
        "{%0,%1,%2,%3}, {%4,%5,%6,%7}, {%8,%9}, {%0,%1,%2,%3};"
        : "+f"(d[0]),"+f"(d[1]),"+f"(d[2]),"+f"(d[3])
        : "r"(a[0]),"r"(a[1]),"r"(a[2]),"r"(a[3]), "r"(b0),"r"(b1));
}

// ================= pure-fp16 tensor-core GEMM (mma.sync, trans-B) =================
// Y[bz, o, p] = sum_k Wh[o,k] * Bh[k,p] (+bias); B from channel-major [bz][c][p].
// CTA tile 128x128, K-chunks of 64, 2-stage cp.async pipeline (champion config).
// EPI 1: sigmoid-gate blend (fn2 out); 2: gelu+pixel-reduce (qp);
// EPI 3: fn1/gate (yd-blend; rowSplit=CC -> f1 path, rowSplit=0 -> gate path);
// EPI 4: fp16 store (yd).
#define KC 64
#define APITCH 144                // A tile row pitch (128B data + 16 pad; conflict-free)
#define A_TILE (128*APITCH)       // 18432
#define BPITCH 272                // B tile row pitch (256B data + 16 pad)
#define B_TILE (KC*BPITCH)        // 17408
#define STAGE_B (A_TILE + B_TILE) // 35840
#define NSTAGE 2

template<int EPI>
__global__ void __launch_bounds__(256,2) gemm_tc(
    const __half* __restrict__ Wh, long long sA,
    const __half* __restrict__ Bh, long long sBpl,
    const float* __restrict__ biasa, const float* __restrict__ biasb, int rowSplit,
    float* __restrict__ Y, long long sY, int Kiter,
    const __half* __restrict__ gate_in,        // EPI1
    const __half* __restrict__ xres,           // EPI1 (fp16 residual)
    __half* __restrict__ gate_out,             // EPI3
    float* __restrict__ gnpart,                // EPI3
    const __half* __restrict__ ydbase,         // EPI3
    float* __restrict__ qpout)                 // EPI2
{
    extern __shared__ char smem[];
    const uint32_t sb = smem_u32(smem);
    const int tid = threadIdx.x, wid = tid >> 5, lane = tid & 31;
    const int warpM = wid >> 2, warpN = wid & 3;
    const int pBase = blockIdx.x * 128, oBase = blockIdx.y * 128, bz = blockIdx.z;
    const long long P = 4096;

    const __half* a_g = Wh + (long long)oBase * sA;
    const __half* b_p = Bh + (long long)bz * sBpl + pBase;

    float acc[4][4][4];
#pragma unroll
    for (int a = 0; a < 4; a++)
#pragma unroll
        for (int b = 0; b < 4; b++)
#pragma unroll
            for (int c = 0; c < 4; c++) acc[a][b][c] = 0.f;

    const uint32_t aoff = (uint32_t)((warpM*64 + (lane & 15)) * APITCH + (lane >> 4) * 16);
    const uint32_t boff4 = (uint32_t)((lane & 15) * BPITCH + ((lane >> 4) << 4) + warpN * 64);

    const int nCh = Kiter / KC;

    auto load_stage = [&](int st, int c0){
        uint32_t base = sb + st * STAGE_B;
#pragma unroll
        for (int i = 0; i < 8; i++){
            int t = tid + (i << 8);
            if (t < 1024){
                int r = t >> 3, ck = t & 7;          // A: 128 rows x 8 chunks of 16B
                cpa16(base + (uint32_t)(r*APITCH + ck*16),
                      a_g + (long long)r * sA + c0 + (ck << 3));
            } else {
                int u = t - 1024, r = u >> 4, ck = u & 15;  // B: 64 k-rows x 16 chunks
                cpa16(base + A_TILE + (uint32_t)(r*BPITCH + ck*16),
                      b_p + (long long)(c0 + r) * P + (ck << 3));
            }
        }
        asm volatile("cp.async.commit_group;" ::: "memory");
    };

    load_stage(0, 0);

    for (int ch = 0; ch < nCh; ch++){
        if (ch + 1 < nCh){
            load_stage((ch + 1) & 1, (ch + 1) * KC);
            asm volatile("cp.async.wait_group 1;" ::: "memory");
        } else {
            asm volatile("cp.async.wait_group 0;" ::: "memory");
        }
        __syncthreads();

        uint32_t base = sb + (ch & 1) * STAGE_B;
        uint32_t SA = base, SB = base + A_TILE;
#pragma unroll
        for (int ks = 0; ks < 4; ks++){
            uint32_t ako = ks * 32;              // 16 fp16 = 32 B along A row
            uint32_t bko = ks * 16 * BPITCH;     // 16 k-rows down B tile
            uint32_t b4a[4], b4b[4];
            ldm_x4t(b4a, SB + boff4 + bko);        // n fragments 0,1
            ldm_x4t(b4b, SB + boff4 + bko + 32);   // n fragments 2,3
#pragma unroll
            for (int mi = 0; mi < 4; mi++){
                uint32_t a[4];
                ldm_x4(a, SA + aoff + mi*16*APITCH + ako);
                mma_f16(acc[mi][0], a, b4a[0], b4a[1]);
                mma_f16(acc[mi][1], a, b4a[2], b4a[3]);
                mma_f16(acc[mi][2], a, b4b[0], b4b[1]);
                mma_f16(acc[mi][3], a, b4b[2], b4b[3]);
            }
        }
        __syncthreads();
    }

    // ---- epilogue: acc -> SMEM stage (pitch 132) -> coalesced out ----
    float* stage = (float*)smem;
#pragma unroll
    for (int mi = 0; mi < 4; mi++){
        int r0 = warpM*64 + mi*16 + (lane >> 2);
#pragma unroll
        for (int ni = 0; ni < 4; ni++){
            int col = warpN*32 + ni*8 + 2*(lane & 3);
            stage[r0*132 + col]       = acc[mi][ni][0];
            stage[r0*132 + col + 1]   = acc[mi][ni][1];
            stage[(r0+8)*132 + col]   = acc[mi][ni][2];
            stage[(r0+8)*132 + col+1] = acc[mi][ni][3];
        }
    }
    __syncthreads();

    if (EPI == 2){
        int r = tid >> 1, h = tid & 1;
        int o = oBase + r;
        float s = 0.f;
        if (o < KDIM){
            float bo = biasa[o];
            const float* row = stage + r * 132 + h * 64;
#pragma unroll 8
            for (int j = 0; j < 64; j++) s += gelu_f(row[j] + bo);
        }
        s += __shfl_xor_sync(0xffffffffu, s, 1);
        if (h == 0 && o < KDIM)
            qpout[((bz*KDIM) + o)*QT + blockIdx.x] = s;
        return;
    }

    if (EPI == 4){
        __half* Yh = (__half*)Y;
        for (int i = tid; i < 128 * 128; i += 256){
            int r = i >> 7, c = i & 127;
            int o = oBase + r;
            Yh[(long long)bz * sY + (long long)o * P + pBase + c]
                = __float2half_rn(stage[r * 132 + c]);
        }
        return;
    }

    if (EPI == 3){
        float a0 = g_attnw[bz*2], a1 = g_attnw[bz*2+1];
        const long long YDS = (long long)2*CC*HW;
        const __half* yd0 = ydbase + (long long)g_attni[bz*2]   * YDS;
        const __half* yd1 = ydbase + (long long)g_attni[bz*2+1] * YDS;
        bool isF1 = (oBase < rowSplit);
        __half* Yh = (__half*)Y;
        for (int i = tid; i < 128 * 128; i += 256){
            int r = i >> 7, c = i & 127;
            int o = oBase + r; long long p = pBase + c;
            long long q = (long long)o * P + p;
            float v = stage[r * 132 + c];
            float bo = (o < rowSplit) ? biasa[o] : biasb[o - rowSplit];
            v += bo + a0 * __half2float(yd0[q]) + a1 * __half2float(yd1[q]);
            if (isF1){
                Yh[(long long)bz * sY + q] = __float2half_rn(v);
                stage[r * 132 + c] = v;          // exact fp32 for GN partials
            } else {
                float g = 1.0f / (1.0f + expf(-v));
                gate_out[((long long)bz * CC + (o - rowSplit)) * P + p] = __float2half_rn(g);
            }
        }
        if (isF1){
            __syncthreads();
            int r = tid >> 1, h = tid & 1;
            const float* row = stage + r * 132 + h * 64;
            float s = 0.f, ss = 0.f;
#pragma unroll 8
            for (int j = 0; j < 64; j++){ float v = row[j]; s += v; ss += v*v; }
            s  += __shfl_xor_sync(0xffffffffu, s, 1);
            ss += __shfl_xor_sync(0xffffffffu, ss, 1);
            if (h == 0){
                int o = oBase + r;
                float* dst = gnpart + ((long long)(bz*CC + o)*32 + blockIdx.x)*2;
                dst[0] = s; dst[1] = ss;
            }
        }
        return;
    }

    // EPI == 1 : fn2 output + sigmoid-gate blend (fp16 gate + fp16 residual)
    for (int i = tid; i < 128 * 128; i += 256){
        int r = i >> 7, c = i & 127;
        float v = stage[r * 132 + c];
        int o = oBase + r; long long p = pBase + c;
        v += biasa[o];
        long long q = ((long long)bz * CC + o) * P + p;
        float g = __half2float(gate_in[q]);
        float xr = __half2float(xres[q]);
        Y[(long long)bz * sY + (long long)o * P + p] = g * v + (1.0f - g) * xr;
    }
}

// ================= conversion helpers =================
__global__ void wconv_all(const float* __restrict__ w1, const float* __restrict__ wg,
                          const float* __restrict__ w2, const float* __restrict__ wq){
    int i = blockIdx.x * 256 + threadIdx.x;
    const int N1 = CC*2*CC, N2 = 2*N1, N3 = N2 + CC*CC, N4 = N3 + 256*CC;
    if (i < N1)      g_wh[i] = __float2half_rn(w1[i]);
    else if (i < N2) g_wh[i] = __float2half_rn(wg[i - N1]);
    else if (i < N3) g_w2h[i - N2] = __float2half_rn(w2[i - N2]);
    else if (i < N4){
        int j = i - N3;
        g_qph[j] = __float2half_rn((j < KDIM*CC) ? wq[j] : 0.f);
    }
}

__global__ void xconv(const float* __restrict__ src, __half* __restrict__ dst){
    long long i4 = (long long)blockIdx.x * 256 + threadIdx.x;
    float4 v = ((const float4*)src)[i4];
    __half2* D = (__half2*)(dst + (i4<<2));
    D[0] = __halves2half2(__float2half_rn(v.x), __float2half_rn(v.y));
    D[1] = __halves2half2(__float2half_rn(v.z), __float2half_rn(v.w));
}

// ---------------- vd GEMM, split-K x4 (writes partials, no bias) ----------------
constexpr int GK = 16;

__global__ __launch_bounds__(256) void vd_gemm(
    const float* __restrict__ Wa,
    const float* __restrict__ Xa, long long sXa)
{
    __shared__ float As[GK][64];
    __shared__ float Bs[GK][64];

    const int tid = threadIdx.x;
    const int tx = tid & 15, ty = tid >> 4;
    const int kc = blockIdx.x;
    const int oBase = blockIdx.y * 64;
    const int m = blockIdx.z;
    const int kBeg = kc * 160;

    float acc[4][4];
#pragma unroll
    for (int i = 0; i < 4; i++)
#pragma unroll
        for (int j = 0; j < 4; j++) acc[i][j] = 0.f;

    for (int c0 = kBeg; c0 < kBeg + 160; c0 += GK){
        {
            int i = tid >> 2;
            int j4 = (tid & 3) << 2;
            float4 w = *(const float4*)(Wa + (long long)(oBase + i)*CC + c0 + j4);
            As[j4+0][i] = w.x; As[j4+1][i] = w.y; As[j4+2][i] = w.z; As[j4+3][i] = w.w;
        }
        {
            int j = tid >> 4;
            int n4 = (tid & 15) << 2;
            const float* xp = Xa + m*sXa + (long long)(c0 + j)*64;
            *(float4*)&Bs[j][n4] = *(const float4*)(xp + n4);
        }
        __syncthreads();
#pragma unroll
        for (int kk = 0; kk < GK; kk++){
            float a[4], b[4];
            float4 t = *(const float4*)&As[kk][ty*4];
            a[0]=t.x; a[1]=t.y; a[2]=t.z; a[3]=t.w;
            float4 u = *(const float4*)&Bs[kk][tx*4];
            b[0]=u.x; b[1]=u.y; b[2]=u.z; b[3]=u.w;
#pragma unroll
            for (int i = 0; i < 4; i++)
#pragma unroll
                for (int j = 0; j < 4; j++)
                    acc[i][j] = fmaf(a[i], b[j], acc[i][j]);
        }
        __syncthreads();
    }

    float* dst = g_tpart + ((long long)(kc*MR + m)*CC)*64;
#pragma unroll
    for (int i = 0; i < 4; i++){
        int o = oBase + ty*4 + i;
        *(float4*)(dst + (long long)o*64 + tx*4) =
            make_float4(acc[i][0], acc[i][1], acc[i][2], acc[i][3]);
    }
}

// ---------------- attention: q reduce, cosine sims, top-2, softmax ----------------
__global__ void attn_kernel(const float* __restrict__ mem_keys){
    __shared__ float qs[BB*KDIM];
    int tid = threadIdx.x;
    for (int idx = tid; idx < BB*KDIM; idx += 256){
        const float* p = g_qp + (long long)idx*QT;
        float s = 0.f;
        for (int t = 0; t < QT; t++) s += p[t];
        qs[idx] = s * (1.0f/4096.0f);
    }
    __syncthreads();
    if (tid < BB){
        int b = tid;
        const float* q = qs + b*KDIM;
        float qn = 0.f;
        for (int j = 0; j < KDIM; j++) qn += q[j]*q[j];
        qn = fmaxf(sqrtf(qn), 1e-12f);
        float v[MR];
        for (int m = 0; m < MR; m++){
            const float* kk = mem_keys + m*KDIM;
            float kn = 0.f, d = 0.f;
            for (int j = 0; j < KDIM; j++){ kn += kk[j]*kk[j]; d += q[j]*kk[j]; }
            kn = fmaxf(sqrtf(kn), 1e-12f);
            v[m] = d/(qn*kn);
        }
        int i0 = 0;
        for (int m = 1; m < MR; m++) if (v[m] > v[i0]) i0 = m;
        int i1 = -1;
        for (int m = 0; m < MR; m++){
            if (m == i0) continue;
            if (i1 < 0 || v[m] > v[i1]) i1 = m;
        }
        float e1 = expf((v[i1]-v[i0])*10.0f);
        float a0 = 1.0f/(1.0f+e1);
        float a1 = e1/(1.0f+e1);
        g_attnw[b*2] = a0; g_attnw[b*2+1] = a1;
        g_attni[b*2] = i0; g_attni[b*2+1] = i1;
    }
}

// ---------------- bilinear 8->64 upsample + gelu + dw3x3 -> fp16 ----------------
__global__ __launch_bounds__(256) void up_gelu_dw(
    const float* __restrict__ wdw, const float* __restrict__ bdw,
    const float* __restrict__ vbias)
{
    int m = blockIdx.x / CC, c = blockIdx.x % CC;
    __shared__ float sm[64][65];
    __shared__ float tt[64];
    int tid = threadIdx.x;
    if (tid < 64){
        float s = vbias[c];
#pragma unroll
        for (int kc = 0; kc < 4; kc++)
            s += g_tpart[((long long)(kc*MR + m)*CC + c)*64 + tid];
        tt[tid] = s;
    }
    __syncthreads();
    for (int i = tid; i < 1024; i += 256){
        int p = i << 2, h = p >> 6, w0 = p & 63;
        float shf = h*0.125f - 0.4375f;
        int ih = (int)floorf(shf);
        float fh = shf - (float)ih;
        int h0 = ih < 0 ? 0 : ih;
        int h1 = (ih+1 > 7) ? 7 : ih+1;
#pragma unroll
        for (int q2 = 0; q2 < 4; q2++){
            int w = w0 + q2;
            float swf = w*0.125f - 0.4375f;
            int iw = (int)floorf(swf);
            float fw = swf - (float)iw;
            int wA = iw < 0 ? 0 : iw;
            int wB = (iw+1 > 7) ? 7 : iw+1;
            float top = (1.f-fw)*tt[h0*8+wA] + fw*tt[h0*8+wB];
            float bot = (1.f-fw)*tt[h1*8+wA] + fw*tt[h1*8+wB];
            float v = (1.f-fh)*top + fh*bot;
            sm[h][w] = gelu_f(v);
        }
    }
    __syncthreads();
    float w9[9];
#pragma unroll
    for (int t = 0; t < 9; t++) w9[t] = wdw[c*9+t];
    float bb = bdw[c];
    __half* dh = g_dech + ((long long)m*CC + c)*HW;
    for (int i = tid; i < 1024; i += 256){
        int p = i << 2, h = p >> 6, w0 = p & 63;
        float ov[4];
#pragma unroll
        for (int q2 = 0; q2 < 4; q2++){
            int w = w0 + q2;
            float s = bb;
#pragma unroll
            for (int ky = 0; ky < 3; ky++){
                int hh = h + ky - 1;
                if ((unsigned)hh > 63u) continue;
#pragma unroll
                for (int kx = 0; kx < 3; kx++){
                    int ww = w + kx - 1;
                    if ((unsigned)ww > 63u) continue;
                    s = fmaf(w9[ky*3+kx], sm[hh][ww], s);
                }
            }
            ov[q2] = s;
        }
        __half2* H = (__half2*)(dh + p);
        H[0] = __halves2half2(__float2half_rn(ov[0]), __float2half_rn(ov[1]));
        H[1] = __halves2half2(__float2half_rn(ov[2]), __float2half_rn(ov[3]));
    }
}

// ---------------- group-norm statistics (reduce fused partials) ----------------
__global__ void gn_stats(){
    int b = blockIdx.x >> 5, g = blockIdx.x & 31;
    int tid = threadIdx.x;
    float s = 0.f, ss = 0.f;
    for (int i = tid; i < CPG*32; i += 256){
        int c = g*CPG + i/32, tx = i%32;
        const float* p = g_gnpart + ((long long)(b*CC + c)*32 + tx)*2;
        s += p[0]; ss += p[1];
    }
    __shared__ float sh1[256], sh2[256];
    sh1[tid] = s; sh2[tid] = ss;
    __syncthreads();
    for (int st = 128; st > 0; st >>= 1){
        if (tid < st){ sh1[tid] += sh1[tid+st]; sh2[tid] += sh2[tid+st]; }
        __syncthreads();
    }
    if (tid == 0){
        const float inv = 1.0f/(CPG*HW);
        float mu = sh1[0]*inv;
        float var = sh2[0]*inv - mu*mu;
        g_gn[blockIdx.x*2]   = mu;
        g_gn[blockIdx.x*2+1] = rsqrtf(var + 1e-5f);
    }
}

// ---------------- group-norm + gelu + depthwise 3x3 (fp16 in/out) ----------------
__global__ __launch_bounds__(256) void gn_gelu_dw(
    const float* __restrict__ gamma, const float* __restrict__ beta,
    const float* __restrict__ wdw, const float* __restrict__ bdw)
{
    int b = blockIdx.x / CC, c = blockIdx.x % CC;
    __shared__ float sm[64][65];
    int tid = threadIdx.x;
    const __half2* src = (const __half2*)(g_f1h + ((long long)b*CC + c)*HW);
    int g = c / CPG;
    float mu = g_gn[(b*GROUPS+g)*2], rs = g_gn[(b*GROUPS+g)*2+1];
    float ga = gamma[c]*rs;
    float be = beta[c] - mu*ga;
    for (int i = tid; i < 1024; i += 256){
        __half2 v01 = src[2*i], v23 = src[2*i+1];
        int p = i << 2, h = p >> 6, w0 = p & 63;
        sm[h][w0]   = gelu_f(__low2float(v01)*ga + be);
        sm[h][w0+1] = gelu_f(__high2float(v01)*ga + be);
        sm[h][w0+2] = gelu_f(__low2float(v23)*ga + be);
        sm[h][w0+3] = gelu_f(__high2float(v23)*ga + be);
    }
    __syncthreads();
    float w9[9];
#pragma unroll
    for (int t = 0; t < 9; t++) w9[t] = wdw[c*9+t];
    float bb = bdw[c];
    __half* dh = g_f2h + ((long long)b*CC + c)*HW;
    for (int i = tid; i < 1024; i += 256){
        int p = i << 2, h = p >> 6, w0 = p & 63;
        float ov[4];
#pragma unroll
        for (int q2 = 0; q2 < 4; q2++){
            int w = w0 + q2;
            float s = bb;
#pragma unroll
            for (int ky = 0; ky < 3; ky++){
                int hh = h + ky - 1;
                if ((unsigned)hh > 63u) continue;
#pragma unroll
                for (int kx = 0; kx < 3; kx++){
                    int ww = w + kx - 1;
                    if ((unsigned)ww > 63u) continue;
                    s = fmaf(w9[ky*3+kx], sm[hh][ww], s);
                }
            }
            ov[q2] = s;
        }
        __half2* H = (__half2*)(dh + p);
        H[0] = __halves2half2(__float2half_rn(ov[0]), __float2half_rn(ov[1]));
        H[1] = __halves2half2(__float2half_rn(ov[2]), __float2half_rn(ov[3]));
    }
}

// ---------------- host launcher ----------------
extern "C" void kernel_launch(void* const* d_in, const int* in_sizes, int n_in,
                              void* d_out, int out_size)
{
    const float* x         = (const float*)d_in[0];
    const float* qp_w      = (const float*)d_in[1];
    const float* qp_b      = (const float*)d_in[2];
    const float* mem_keys  = (const float*)d_in[3];
    const float* mem_values= (const float*)d_in[4];
    const float* vd_w1     = (const float*)d_in[5];
    const float* vd_b1     = (const float*)d_in[6];
    const float* vd_wdw    = (const float*)d_in[7];
    const float* vd_bdw    = (const float*)d_in[8];
    const float* fn_w1     = (const float*)d_in[9];
    const float* fn_b1     = (const float*)d_in[10];
    const float* fn_gamma  = (const float*)d_in[11];
    const float* fn_beta   = (const float*)d_in[12];
    const float* fn_wdw    = (const float*)d_in[13];
    const float* fn_bdw    = (const float*)d_in[14];
    const float* fn_w2     = (const float*)d_in[15];
    const float* fn_b2     = (const float*)d_in[16];
    const float* fg_w      = (const float*)d_in[17];
    const float* fg_b      = (const float*)d_in[18];
    float* out = (float*)d_out;
    (void)in_sizes; (void)n_in; (void)out_size;

    float *p_qp, *p_zeros, *p_gnpart;
    __half *p_wh, *p_w2h, *p_qph, *p_xh, *p_dech, *p_ydh, *p_f1h, *p_gate, *p_f2h;
    cudaGetSymbolAddress((void**)&p_qp,    g_qp);
    cudaGetSymbolAddress((void**)&p_zeros, g_zeros);
    cudaGetSymbolAddress((void**)&p_gnpart,g_gnpart);
    cudaGetSymbolAddress((void**)&p_wh,    g_wh);
    cudaGetSymbolAddress((void**)&p_w2h,   g_w2h);
    cudaGetSymbolAddress((void**)&p_qph,   g_qph);
    cudaGetSymbolAddress((void**)&p_xh,    g_xh);
    cudaGetSymbolAddress((void**)&p_dech,  g_dech);
    cudaGetSymbolAddress((void**)&p_ydh,   g_ydh);
    cudaGetSymbolAddress((void**)&p_f1h,   g_f1h);
    cudaGetSymbolAddress((void**)&p_gate,  g_gate);
    cudaGetSymbolAddress((void**)&p_f2h,   g_f2h);

    const int DSM = NSTAGE * STAGE_B;   // 71680 (epilogue stage 67584 fits)
    cudaFuncSetAttribute(gemm_tc<1>, cudaFuncAttributeMaxDynamicSharedMemorySize, DSM);
    cudaFuncSetAttribute(gemm_tc<2>, cudaFuncAttributeMaxDynamicSharedMemorySize, DSM);
    cudaFuncSetAttribute(gemm_tc<3>, cudaFuncAttributeMaxDynamicSharedMemorySize, DSM);
    cudaFuncSetAttribute(gemm_tc<4>, cudaFuncAttributeMaxDynamicSharedMemorySize, DSM);

    const long long sX = (long long)CC*HW;

    // side stream + fork/join events (capture-legal; fresh per call)
    cudaStream_t s1;
    cudaStreamCreateWithFlags(&s1, cudaStreamNonBlocking);
    cudaEvent_t e0, e1, e2, e3;
    cudaEventCreateWithFlags(&e0, cudaEventDisableTiming);
    cudaEventCreateWithFlags(&e1, cudaEventDisableTiming);
    cudaEventCreateWithFlags(&e2, cudaEventDisableTiming);
    cudaEventCreateWithFlags(&e3, cudaEventDisableTiming);

    // chain B front (s1): vd split-K + upsample/dw need NO converted weights
    vd_gemm<<<dim3(4,10,MR),256,0,s1>>>(vd_w1, mem_values, (long long)CC*64);
    up_gelu_dw<<<MR*CC,256,0,s1>>>(vd_wdw, vd_bdw, vd_b1);

    // stream 0: weight conversions, then signal e0 (Yd GEMM needs g_wh)
    {
        const int NTOT = 2*(CC*2*CC) + CC*CC + 256*CC;
        wconv_all<<<(NTOT+255)/256,256>>>(fn_w1, fg_w, fn_w2, qp_w);
    }
    cudaEventRecord(e0, 0);
    cudaStreamWaitEvent(s1, e0, 0);

    // chain B tail (s1): Yd GEMM
    gemm_tc<4><<<dim3(32,10,MR),256,DSM,s1>>>(
        p_wh + CC, 2*CC,
        p_dech, sX,
        p_zeros, p_zeros, 2*CC,
        (float*)p_ydh, (long long)2*CC*HW, CC,
        nullptr, nullptr, nullptr, nullptr, nullptr, nullptr);
    cudaEventRecord(e1, s1);

    // chain A (stream 0): x fp16 -> qp GEMM -> attention
    xconv<<<(int)((long long)BB*CC*HW/4/256),256>>>(x, p_xh);
    gemm_tc<2><<<dim3(QT,2,BB),256,DSM>>>(
        p_qph, CC, p_xh, sX,
        qp_b, qp_b, KDIM,
        nullptr, 0, CC,
        nullptr, nullptr, nullptr, nullptr, nullptr, p_qp);
    attn_kernel<<<1,256>>>(mem_keys);
    cudaEventRecord(e2, 0);

    // gate half of fn1 on s1 (after Yd + chain A): rows 640..1279 of W,
    // rowSplit=0 -> gate branch, ydbase offset to gate rows.
    cudaStreamWaitEvent(s1, e2, 0);
    gemm_tc<3><<<dim3(32,5,BB),256,DSM,s1>>>(
        p_wh + (long long)CC * (2*CC), 2*CC,
        p_xh, sX,
        fg_b, fg_b, 0,
        nullptr, 0, CC,
        nullptr, nullptr, p_gate, p_gnpart, p_ydh + (long long)CC*HW, nullptr);
    cudaEventRecord(e3, s1);

    // f1 half of fn1 on stream 0 (after Yd): rows 0..639, GN partials + f1 store
    cudaStreamWaitEvent(0, e1, 0);
    gemm_tc<3><<<dim3(32,5,BB),256,DSM>>>(
        p_wh, 2*CC,
        p_xh, sX,
        fn_b1, fn_b1, CC,
        (float*)p_f1h, sX, CC,
        nullptr, nullptr, nullptr, p_gnpart, p_ydh, nullptr);

    // GN chain (stream 0) — overlaps the gate half's tail on s1
    gn_stats<<<BB*GROUPS,256>>>();
    gn_gelu_dw<<<BB*CC,256>>>(fn_gamma, fn_beta, fn_wdw, fn_bdw);

    // join gate before fn2
    cudaStreamWaitEvent(0, e3, 0);

    // fn2 GEMM + sigmoid-gate blend -> out
    gemm_tc<1><<<dim3(32,5,BB),256,DSM>>>(
        p_w2h, CC,
        p_f2h, sX,
        fn_b2, fn_b2, CC,
        out, sX, CC,
        p_gate, p_xh, nullptr, nullptr, nullptr, nullptr);
}